// round 1
// baseline (speedup 1.0000x reference)
#include <cuda_runtime.h>
#include <math.h>

#define BB   4
#define CC   64
#define HH   192
#define WW   192
#define HWX  (HH*WW)
#define OFFC 18
#define HID  4

// scratch (device globals; allocations are forbidden)
__device__ float g_off[BB*OFFC*HH*WW];   // 10.6 MB
__device__ float g_h  [BB*CC*HH*WW];     // 37.7 MB
__device__ float g_pool[BB*CC];
__device__ float g_cw  [BB*CC];
__device__ float g_sw  [BB*HH*WW];

// ---------------------------------------------------------------------------
// K1: 3x3 conv 64 -> 18 (offset prediction), pad 1
// block = 256 threads, tile 32x8; grid (6, 24, 4)
// ---------------------------------------------------------------------------
__global__ __launch_bounds__(256) void offset_conv_kernel(
        const float* __restrict__ x,
        const float* __restrict__ off_w,
        const float* __restrict__ off_b) {
    __shared__ float wsm[OFFC*CC*9];   // 10368 floats = 41.5 KB
    __shared__ float xs[10*34];

    const int tid = threadIdx.x;
    const int bx = blockIdx.x, by = blockIdx.y, b = blockIdx.z;
    const int lx = tid & 31, ly = tid >> 5;
    const int xg = bx*32 + lx, yg = by*8 + ly;

    for (int t = tid; t < OFFC*CC*9; t += 256) wsm[t] = off_w[t];

    float acc[OFFC];
    #pragma unroll
    for (int o = 0; o < OFFC; ++o) acc[o] = off_b[o];

    const float* xb = x + (size_t)b*CC*HWX;

    #pragma unroll 1
    for (int c = 0; c < CC; ++c) {
        __syncthreads();
        for (int t = tid; t < 340; t += 256) {
            int r = t / 34, q = t % 34;
            int gy = by*8 + r - 1, gx = bx*32 + q - 1;
            float v = 0.f;
            if (gy >= 0 && gy < HH && gx >= 0 && gx < WW)
                v = xb[c*HWX + gy*WW + gx];
            xs[t] = v;
        }
        __syncthreads();
        float xv[9];
        #pragma unroll
        for (int i = 0; i < 3; ++i)
            #pragma unroll
            for (int j = 0; j < 3; ++j)
                xv[i*3+j] = xs[(ly+i)*34 + lx + j];
        const float* wc = wsm + c*9;
        #pragma unroll
        for (int o = 0; o < OFFC; ++o) {
            const float* w = wc + o*CC*9;
            #pragma unroll
            for (int t = 0; t < 9; ++t) acc[o] += xv[t] * w[t];
        }
    }
    #pragma unroll
    for (int o = 0; o < OFFC; ++o)
        g_off[((b*OFFC + o)*HH + yg)*WW + xg] = acc[o];
}

// ---------------------------------------------------------------------------
// K2: deformable 3x3 conv 64->64 + BatchNorm epilogue
// block = 256 threads; 32 consecutive pixels of one row x all 64 out channels
// grid (6, 192, 4)
// ---------------------------------------------------------------------------
__global__ __launch_bounds__(256) void deform_bn_kernel(
        const float* __restrict__ x,
        const float* __restrict__ dw,
        const float* __restrict__ db,
        const float* __restrict__ gma,
        const float* __restrict__ bta,
        const float* __restrict__ mean,
        const float* __restrict__ var) {
    __shared__ __align__(16) float dw_s[CC*CC];   // [o][c], one tap: 16 KB
    __shared__ float samp_s[CC*33];               // [c][pixel], padded: conflict-free
    __shared__ float m_wy[32], m_wx[32];
    __shared__ int   m_y0[32], m_x0[32];

    const int tid = threadIdx.x;
    const int b  = blockIdx.z;
    const int y  = blockIdx.y;
    const int x0b = blockIdx.x * 32;
    const int p  = tid & 31;         // pixel within tile (= lane)
    const int og = tid >> 5;         // output-channel group 0..7 (= warp)
    const int xg = x0b + p;

    float acc[8];
    #pragma unroll
    for (int r = 0; r < 8; ++r) acc[r] = db[og*8 + r];

    const float* xb   = x     + (size_t)b*CC*HWX;
    const float* offb = g_off + (size_t)b*OFFC*HWX;

    #pragma unroll 1
    for (int kk = 0; kk < 9; ++kk) {
        const int i = kk / 3, j = kk % 3;
        __syncthreads();   // previous tap's smem reads are done
        if (tid < 32) {
            float oy = offb[(2*kk  )*HWX + y*WW + xg];
            float ox = offb[(2*kk+1)*HWX + y*WW + xg];
            float py = (float)(y  + i - 1) + oy;
            float px = (float)(xg + j - 1) + ox;
            float fy = floorf(py), fx = floorf(px);
            m_y0[p] = (int)fy;  m_x0[p] = (int)fx;
            m_wy[p] = py - fy;  m_wx[p] = px - fx;
        }
        // load this tap's 64x64 weight slice
        for (int t = tid; t < CC*CC; t += 256) {
            int o = t >> 6, c = t & 63;
            dw_s[t] = dw[(o*CC + c)*9 + kk];
        }
        __syncthreads();

        // bilinear gather: 2048 samples, 8 per thread; lane == pixel -> coalesced
        #pragma unroll
        for (int r = 0; r < 8; ++r) {
            int s = r*256 + tid;
            int c = s >> 5, pp = s & 31;
            int  y0 = m_y0[pp], xq = m_x0[pp];
            float wy = m_wy[pp], wx = m_wx[pp];
            const float* xc = xb + c*HWX;
            float v = 0.f;
            bool y0v = (unsigned)y0       < (unsigned)HH;
            bool y1v = (unsigned)(y0 + 1) < (unsigned)HH;
            bool x0v = (unsigned)xq       < (unsigned)WW;
            bool x1v = (unsigned)(xq + 1) < (unsigned)WW;
            if (y0v && x0v) v += (1.f-wy)*(1.f-wx) * xc[y0*WW + xq];
            if (y0v && x1v) v += (1.f-wy)*wx       * xc[y0*WW + xq + 1];
            if (y1v && x0v) v += wy*(1.f-wx)       * xc[(y0+1)*WW + xq];
            if (y1v && x1v) v += wy*wx             * xc[(y0+1)*WW + xq + 1];
            samp_s[c*33 + pp] = v;
        }
        __syncthreads();

        // register-tiled GEMM: acc[o] += dw[o][c] * samp[c][p]
        const float4* dw4 = reinterpret_cast<const float4*>(dw_s);
        #pragma unroll
        for (int c4 = 0; c4 < 16; ++c4) {
            float s0 = samp_s[(4*c4+0)*33 + p];
            float s1 = samp_s[(4*c4+1)*33 + p];
            float s2 = samp_s[(4*c4+2)*33 + p];
            float s3 = samp_s[(4*c4+3)*33 + p];
            #pragma unroll
            for (int r = 0; r < 8; ++r) {
                float4 w = dw4[(og*8 + r)*16 + c4];
                acc[r] += w.x*s0 + w.y*s1 + w.z*s2 + w.w*s3;
            }
        }
    }

    #pragma unroll
    for (int r = 0; r < 8; ++r) {
        int o = og*8 + r;
        float inv = rsqrtf(var[o] + 1e-5f);
        float v = (acc[r] - mean[o]) * (gma[o] * inv) + bta[o];
        g_h[((b*CC + o)*HH + y)*WW + xg] = v;
    }
}

// ---------------------------------------------------------------------------
// K3: global average pool per (b, c): 256 blocks x 256 threads
// ---------------------------------------------------------------------------
__global__ __launch_bounds__(256) void pool_kernel() {
    const int bc = blockIdx.x;
    const float* hp = g_h + (size_t)bc*HWX;
    float s = 0.f;
    for (int i = threadIdx.x; i < HWX; i += 256) s += hp[i];
    __shared__ float red[256];
    red[threadIdx.x] = s;
    __syncthreads();
    for (int st = 128; st > 0; st >>= 1) {
        if (threadIdx.x < st) red[threadIdx.x] += red[threadIdx.x + st];
        __syncthreads();
    }
    if (threadIdx.x == 0) g_pool[bc] = red[0] * (1.f/(float)HWX);
}

// ---------------------------------------------------------------------------
// K4: SE MLP (hid=4): one block
// ---------------------------------------------------------------------------
__global__ __launch_bounds__(256) void ca_kernel(
        const float* __restrict__ w1, const float* __restrict__ b1,
        const float* __restrict__ w2, const float* __restrict__ b2) {
    __shared__ float t[BB*HID];
    const int tid = threadIdx.x;
    const int b = tid >> 6, c = tid & 63;
    if (c < HID) {
        float s = b1[c];
        for (int cc = 0; cc < CC; ++cc) s += w1[c*CC + cc] * g_pool[b*CC + cc];
        t[b*HID + c] = fmaxf(s, 0.f);
    }
    __syncthreads();
    float s = b2[c];
    #pragma unroll
    for (int h = 0; h < HID; ++h) s += w2[c*HID + h] * t[b*HID + h];
    g_cw[tid] = 1.f / (1.f + expf(-s));
}

// ---------------------------------------------------------------------------
// K5: spatial attention 7x7 conv over (h * cw) -> sigmoid map
// block 256 threads, tile 32x8; grid (6, 24, 4)
// ---------------------------------------------------------------------------
__global__ __launch_bounds__(256) void sa_kernel(
        const float* __restrict__ sa_w, const float* __restrict__ sa_b) {
    __shared__ float ws[CC*49];
    __shared__ float xs[14*38];
    const int tid = threadIdx.x;
    const int bx = blockIdx.x, by = blockIdx.y, b = blockIdx.z;
    const int lx = tid & 31, ly = tid >> 5;
    const int xg = bx*32 + lx, yg = by*8 + ly;

    for (int t = tid; t < CC*49; t += 256) ws[t] = sa_w[t];

    float acc = sa_b[0];
    const float* hb = g_h + (size_t)b*CC*HWX;

    #pragma unroll 1
    for (int c = 0; c < CC; ++c) {
        float cw = g_cw[b*CC + c];
        __syncthreads();
        for (int t = tid; t < 14*38; t += 256) {
            int r = t / 38, q = t % 38;
            int gy = by*8 + r - 3, gx = bx*32 + q - 3;
            float v = 0.f;
            if (gy >= 0 && gy < HH && gx >= 0 && gx < WW)
                v = hb[c*HWX + gy*WW + gx];
            xs[t] = v;
        }
        __syncthreads();
        float s = 0.f;
        #pragma unroll
        for (int dy = 0; dy < 7; ++dy)
            #pragma unroll
            for (int dx = 0; dx < 7; ++dx)
                s += xs[(ly+dy)*38 + lx+dx] * ws[c*49 + dy*7 + dx];
        acc += s * cw;
    }
    g_sw[(b*HH + yg)*WW + xg] = 1.f / (1.f + expf(-acc));
}

// ---------------------------------------------------------------------------
// K6: out = h * cw * sw
// ---------------------------------------------------------------------------
__global__ __launch_bounds__(256) void finalize_kernel(float* __restrict__ out) {
    int idx = blockIdx.x*256 + threadIdx.x;
    if (idx >= BB*CC*HWX) return;
    int sp = idx % HWX;
    int bc = idx / HWX;
    int b  = bc >> 6;
    out[idx] = g_h[idx] * g_cw[bc] * g_sw[b*HWX + sp];
}

// ---------------------------------------------------------------------------
extern "C" void kernel_launch(void* const* d_in, const int* in_sizes, int n_in,
                              void* d_out, int out_size) {
    const float* x      = (const float*)d_in[0];
    const float* off_w  = (const float*)d_in[1];
    const float* off_b  = (const float*)d_in[2];
    const float* dw     = (const float*)d_in[3];
    const float* db     = (const float*)d_in[4];
    const float* bn_g   = (const float*)d_in[5];
    const float* bn_b   = (const float*)d_in[6];
    const float* bn_m   = (const float*)d_in[7];
    const float* bn_v   = (const float*)d_in[8];
    const float* ca_w1  = (const float*)d_in[9];
    const float* ca_b1  = (const float*)d_in[10];
    const float* ca_w2  = (const float*)d_in[11];
    const float* ca_b2  = (const float*)d_in[12];
    const float* sa_w   = (const float*)d_in[13];
    const float* sa_b   = (const float*)d_in[14];
    float* out = (float*)d_out;

    offset_conv_kernel<<<dim3(WW/32, HH/8, BB), 256>>>(x, off_w, off_b);
    deform_bn_kernel  <<<dim3(WW/32, HH,   BB), 256>>>(x, dw, db, bn_g, bn_b, bn_m, bn_v);
    pool_kernel       <<<BB*CC, 256>>>();
    ca_kernel         <<<1, 256>>>(ca_w1, ca_b1, ca_w2, ca_b2);
    sa_kernel         <<<dim3(WW/32, HH/8, BB), 256>>>(sa_w, sa_b);
    finalize_kernel   <<<(BB*CC*HWX + 255)/256, 256>>>(out);
}

// round 2
// speedup vs baseline: 1.4413x; 1.4413x over previous
#include <cuda_runtime.h>
#include <math.h>

#define BB   4
#define CC   64
#define HH   192
#define WW   192
#define HWX  (HH*WW)
#define OFFC 18
#define HID  4

// scratch (device globals; allocations are forbidden)
__device__ float g_off[BB*OFFC*HH*WW];        // 10.6 MB
__device__ float g_h  [BB*CC*HH*WW];          // 37.7 MB
__device__ float g_pool[BB*CC];
__device__ float g_cw  [BB*CC];
__device__ float g_sw  [BB*HH*WW];
__device__ float g_dwT  [9*CC*CC];            // [kk][o][c]
__device__ float g_offwT[CC*9*OFFC];          // [(c*9+t)*18 + o]

// ---------------------------------------------------------------------------
// K0: weight transposes (once per launch; tiny)
// ---------------------------------------------------------------------------
__global__ __launch_bounds__(256) void transpose_w_kernel(
        const float* __restrict__ dw, const float* __restrict__ off_w) {
    int d = blockIdx.x*256 + threadIdx.x;
    if (d < 9*CC*CC) {
        int kk = d >> 12;          // /4096
        int o  = (d >> 6) & 63;
        int c  = d & 63;
        g_dwT[d] = dw[(o*CC + c)*9 + kk];
    } else {
        int e = d - 9*CC*CC;
        if (e < CC*9*OFFC) {
            int k = e / OFFC;      // c*9+t
            int o = e % OFFC;
            int c = k / 9, t = k % 9;
            g_offwT[e] = off_w[(o*CC + c)*9 + t];
        }
    }
}

// ---------------------------------------------------------------------------
// K1: 3x3 conv 64 -> 18 (offset prediction), pad 1
// tile 64x8, 256 threads, 2 pixels/thread (x and x+32); grid (3, 24, 4)
// ---------------------------------------------------------------------------
__global__ __launch_bounds__(256) void offset_conv_kernel(
        const float* __restrict__ x,
        const float* __restrict__ off_b) {
    __shared__ float wsm[CC*9*OFFC];   // 10368 floats = 41.5 KB, [(c*9+t)*18+o]
    __shared__ float xs[10*66];        // halo tile

    const int tid = threadIdx.x;
    const int bx = blockIdx.x, by = blockIdx.y, b = blockIdx.z;
    const int lx = tid & 31, ly = tid >> 5;
    const int xg0 = bx*64 + lx;        // pixel A
    const int yg = by*8 + ly;

    for (int t = tid; t < CC*9*OFFC/4; t += 256)
        ((float4*)wsm)[t] = ((const float4*)g_offwT)[t];

    float acc[OFFC][2];
    #pragma unroll
    for (int o = 0; o < OFFC; ++o) { float bv = off_b[o]; acc[o][0] = bv; acc[o][1] = bv; }

    const float* xb = x + (size_t)b*CC*HWX;

    #pragma unroll 1
    for (int c = 0; c < CC; ++c) {
        __syncthreads();
        for (int t = tid; t < 660; t += 256) {
            int r = t / 66, q = t % 66;
            int gy = by*8 + r - 1, gx = bx*64 + q - 1;
            float v = 0.f;
            if (gy >= 0 && gy < HH && gx >= 0 && gx < WW)
                v = xb[c*HWX + gy*WW + gx];
            xs[t] = v;
        }
        __syncthreads();
        const float* wc = wsm + c*9*OFFC;
        #pragma unroll
        for (int t = 0; t < 9; ++t) {
            int i = t/3, j = t%3;
            float xa = xs[(ly+i)*66 + lx + j];
            float xc2 = xs[(ly+i)*66 + lx + 32 + j];
            const float2* w2 = (const float2*)(wc + t*OFFC);
            #pragma unroll
            for (int o2 = 0; o2 < 9; ++o2) {
                float2 w = w2[o2];
                acc[2*o2  ][0] += w.x*xa; acc[2*o2  ][1] += w.x*xc2;
                acc[2*o2+1][0] += w.y*xa; acc[2*o2+1][1] += w.y*xc2;
            }
        }
    }
    #pragma unroll
    for (int o = 0; o < OFFC; ++o) {
        g_off[((b*OFFC + o)*HH + yg)*WW + xg0     ] = acc[o][0];
        g_off[((b*OFFC + o)*HH + yg)*WW + xg0 + 32] = acc[o][1];
    }
}

// ---------------------------------------------------------------------------
// K2: deformable 3x3 conv 64->64 + BatchNorm epilogue
// 64 pixels of one row x 64 out channels per block; 256 threads,
// 2 adjacent pixels x 8 outputs per thread; grid (3, 192, 4)
// ---------------------------------------------------------------------------
__global__ __launch_bounds__(256) void deform_bn_kernel(
        const float* __restrict__ x,
        const float* __restrict__ db,
        const float* __restrict__ gma,
        const float* __restrict__ bta,
        const float* __restrict__ mean,
        const float* __restrict__ var) {
    __shared__ __align__(16) float dw_s[CC*CC];     // one tap [o][c]: 16 KB
    __shared__ float samp_s[CC*66];                 // [c][pixel], padded
    __shared__ float m_wy[9*64], m_wx[9*64];
    __shared__ int   m_y0[9*64], m_x0[9*64];

    const int tid = threadIdx.x;
    const int b   = blockIdx.z;
    const int y   = blockIdx.y;
    const int x0b = blockIdx.x * 64;
    const int pq  = tid & 31;        // pixel-pair index (pixels 2pq, 2pq+1)
    const int og  = tid >> 5;        // output-channel group 0..7
    const int ppg = tid & 63;        // gather pixel
    const int cg  = tid >> 6;        // gather channel sub-index 0..3

    const float* xb   = x     + (size_t)b*CC*HWX;
    const float* offb = g_off + (size_t)b*OFFC*HWX;

    // per-block bilinear metadata for all 9 taps x 64 pixels
    for (int t = tid; t < 9*64; t += 256) {
        int kk = t >> 6, p = t & 63;
        int i = kk/3, j = kk%3;
        float oy = offb[(2*kk  )*HWX + y*WW + x0b + p];
        float ox = offb[(2*kk+1)*HWX + y*WW + x0b + p];
        float py = (float)(y  + i - 1) + oy;
        float px = (float)(x0b + p + j - 1) + ox;
        float fy = floorf(py), fx = floorf(px);
        m_y0[t] = (int)fy;  m_x0[t] = (int)fx;
        m_wy[t] = py - fy;  m_wx[t] = px - fx;
    }

    float acc[8][2];
    #pragma unroll
    for (int r = 0; r < 8; ++r) { float bv = db[og*8 + r]; acc[r][0] = bv; acc[r][1] = bv; }

    __syncthreads();

    #pragma unroll 1
    for (int kk = 0; kk < 9; ++kk) {
        // ---- gather this tap's 64x64 samples (16 per thread, fixed pixel) ----
        {
            int mi = kk*64 + ppg;
            int y0 = m_y0[mi], xq = m_x0[mi];
            float wy = m_wy[mi], wx = m_wx[mi];
            float vy0 = ((unsigned)y0     < (unsigned)HH) ? 1.f : 0.f;
            float vy1 = ((unsigned)(y0+1) < (unsigned)HH) ? 1.f : 0.f;
            float vx0 = ((unsigned)xq     < (unsigned)WW) ? 1.f : 0.f;
            float vx1 = ((unsigned)(xq+1) < (unsigned)WW) ? 1.f : 0.f;
            float w00 = (1.f-wy)*(1.f-wx)*vy0*vx0;
            float w01 = (1.f-wy)*wx      *vy0*vx1;
            float w10 = wy*(1.f-wx)      *vy1*vx0;
            float w11 = wy*wx            *vy1*vx1;
            int yc0 = min(max(y0,   0), HH-1);
            int yc1 = min(max(y0+1, 0), HH-1);
            int xc0 = min(max(xq,   0), WW-1);
            int xc1 = min(max(xq+1, 0), WW-1);
            int o00 = yc0*WW + xc0, o01 = yc0*WW + xc1;
            int o10 = yc1*WW + xc0, o11 = yc1*WW + xc1;
            const float* xc = xb + cg*HWX;
            #pragma unroll
            for (int r = 0; r < 16; ++r) {
                float v = w00*xc[o00] + w01*xc[o01] + w10*xc[o10] + w11*xc[o11];
                samp_s[(r*4 + cg)*66 + ppg] = v;
                xc += 4*HWX;
            }
        }
        // ---- stage this tap's weights (coalesced from pre-transposed) ----
        for (int t = tid; t < 1024; t += 256)
            ((float4*)dw_s)[t] = ((const float4*)g_dwT)[kk*1024 + t];
        __syncthreads();

        // ---- register-tiled GEMM: acc[o][p] += dw[o][c] * samp[c][p] ----
        const float4* dw4 = (const float4*)dw_s;
        #pragma unroll
        for (int c4 = 0; c4 < 16; ++c4) {
            float2 s0 = *(const float2*)&samp_s[(4*c4+0)*66 + 2*pq];
            float2 s1 = *(const float2*)&samp_s[(4*c4+1)*66 + 2*pq];
            float2 s2 = *(const float2*)&samp_s[(4*c4+2)*66 + 2*pq];
            float2 s3 = *(const float2*)&samp_s[(4*c4+3)*66 + 2*pq];
            #pragma unroll
            for (int r = 0; r < 8; ++r) {
                float4 w = dw4[(og*8 + r)*16 + c4];
                acc[r][0] += w.x*s0.x + w.y*s1.x + w.z*s2.x + w.w*s3.x;
                acc[r][1] += w.x*s0.y + w.y*s1.y + w.z*s2.y + w.w*s3.y;
            }
        }
        __syncthreads();
    }

    #pragma unroll
    for (int r = 0; r < 8; ++r) {
        int o = og*8 + r;
        float inv = rsqrtf(var[o] + 1e-5f);
        float sc = gma[o]*inv, mu = mean[o], bt = bta[o];
        float2 v;
        v.x = (acc[r][0] - mu)*sc + bt;
        v.y = (acc[r][1] - mu)*sc + bt;
        *(float2*)&g_h[((b*CC + o)*HH + y)*WW + x0b + 2*pq] = v;
    }
}

// ---------------------------------------------------------------------------
// K3: global average pool per (b, c)
// ---------------------------------------------------------------------------
__global__ __launch_bounds__(256) void pool_kernel() {
    const int bc = blockIdx.x;
    const float4* hp = (const float4*)(g_h + (size_t)bc*HWX);
    float s = 0.f;
    for (int i = threadIdx.x; i < HWX/4; i += 256) {
        float4 v = hp[i];
        s += (v.x + v.y) + (v.z + v.w);
    }
    __shared__ float red[256];
    red[threadIdx.x] = s;
    __syncthreads();
    for (int st = 128; st > 0; st >>= 1) {
        if (threadIdx.x < st) red[threadIdx.x] += red[threadIdx.x + st];
        __syncthreads();
    }
    if (threadIdx.x == 0) g_pool[bc] = red[0] * (1.f/(float)HWX);
}

// ---------------------------------------------------------------------------
// K4: SE MLP (hid=4): one block
// ---------------------------------------------------------------------------
__global__ __launch_bounds__(256) void ca_kernel(
        const float* __restrict__ w1, const float* __restrict__ b1,
        const float* __restrict__ w2, const float* __restrict__ b2) {
    __shared__ float t[BB*HID];
    const int tid = threadIdx.x;
    const int b = tid >> 6, c = tid & 63;
    if (c < HID) {
        float s = b1[c];
        for (int cc = 0; cc < CC; ++cc) s += w1[c*CC + cc] * g_pool[b*CC + cc];
        t[b*HID + c] = fmaxf(s, 0.f);
    }
    __syncthreads();
    float s = b2[c];
    #pragma unroll
    for (int h = 0; h < HID; ++h) s += w2[c*HID + h] * t[b*HID + h];
    g_cw[tid] = 1.f / (1.f + expf(-s));
}

// ---------------------------------------------------------------------------
// K5: spatial attention 7x7 conv over (h * cw) -> sigmoid map
// tile 64x8, 256 threads, 2 pixels/thread (x and x+32); grid (3, 24, 4)
// ---------------------------------------------------------------------------
__global__ __launch_bounds__(256) void sa_kernel(
        const float* __restrict__ sa_w, const float* __restrict__ sa_b) {
    __shared__ float ws[CC*49];
    __shared__ float xs[14*70];
    const int tid = threadIdx.x;
    const int bx = blockIdx.x, by = blockIdx.y, b = blockIdx.z;
    const int lx = tid & 31, ly = tid >> 5;
    const int xg0 = bx*64 + lx, yg = by*8 + ly;

    for (int t = tid; t < CC*49; t += 256) ws[t] = sa_w[t];

    float acc0 = sa_b[0], acc1 = sa_b[0];
    const float* hb = g_h + (size_t)b*CC*HWX;

    #pragma unroll 1
    for (int c = 0; c < CC; ++c) {
        float cw = g_cw[b*CC + c];
        __syncthreads();
        for (int t = tid; t < 14*70; t += 256) {
            int r = t / 70, q = t % 70;
            int gy = by*8 + r - 3, gx = bx*64 + q - 3;
            float v = 0.f;
            if (gy >= 0 && gy < HH && gx >= 0 && gx < WW)
                v = hb[c*HWX + gy*WW + gx];
            xs[t] = v;
        }
        __syncthreads();
        float s0 = 0.f, s1 = 0.f;
        #pragma unroll
        for (int dy = 0; dy < 7; ++dy) {
            #pragma unroll
            for (int dx = 0; dx < 7; ++dx) {
                float w = ws[c*49 + dy*7 + dx];
                s0 += xs[(ly+dy)*70 + lx + dx     ] * w;
                s1 += xs[(ly+dy)*70 + lx + 32 + dx] * w;
            }
        }
        acc0 += s0 * cw;
        acc1 += s1 * cw;
    }
    g_sw[(b*HH + yg)*WW + xg0     ] = 1.f / (1.f + expf(-acc0));
    g_sw[(b*HH + yg)*WW + xg0 + 32] = 1.f / (1.f + expf(-acc1));
}

// ---------------------------------------------------------------------------
// K6: out = h * cw * sw  (float4)
// ---------------------------------------------------------------------------
__global__ __launch_bounds__(256) void finalize_kernel(float* __restrict__ out) {
    int idx = blockIdx.x*256 + threadIdx.x;          // float4 index
    if (idx >= BB*CC*HWX/4) return;
    int sp4 = idx % (HWX/4);
    int bc  = idx / (HWX/4);
    int b   = bc >> 6;
    float cw = g_cw[bc];
    float4 h = ((const float4*)g_h)[idx];
    float4 sw = ((const float4*)g_sw)[b*(HWX/4) + sp4];
    float4 o;
    o.x = h.x*cw*sw.x; o.y = h.y*cw*sw.y; o.z = h.z*cw*sw.z; o.w = h.w*cw*sw.w;
    ((float4*)out)[idx] = o;
}

// ---------------------------------------------------------------------------
extern "C" void kernel_launch(void* const* d_in, const int* in_sizes, int n_in,
                              void* d_out, int out_size) {
    const float* x      = (const float*)d_in[0];
    const float* off_w  = (const float*)d_in[1];
    const float* off_b  = (const float*)d_in[2];
    const float* dw     = (const float*)d_in[3];
    const float* db     = (const float*)d_in[4];
    const float* bn_g   = (const float*)d_in[5];
    const float* bn_b   = (const float*)d_in[6];
    const float* bn_m   = (const float*)d_in[7];
    const float* bn_v   = (const float*)d_in[8];
    const float* ca_w1  = (const float*)d_in[9];
    const float* ca_b1  = (const float*)d_in[10];
    const float* ca_w2  = (const float*)d_in[11];
    const float* ca_b2  = (const float*)d_in[12];
    const float* sa_w   = (const float*)d_in[13];
    const float* sa_b   = (const float*)d_in[14];
    float* out = (float*)d_out;

    transpose_w_kernel<<<(9*CC*CC + CC*9*OFFC + 255)/256, 256>>>(dw, off_w);
    offset_conv_kernel<<<dim3(WW/64, HH/8, BB), 256>>>(x, off_b);
    deform_bn_kernel  <<<dim3(WW/64, HH,   BB), 256>>>(x, db, bn_g, bn_b, bn_m, bn_v);
    pool_kernel       <<<BB*CC, 256>>>();
    ca_kernel         <<<1, 256>>>(ca_w1, ca_b1, ca_w2, ca_b2);
    sa_kernel         <<<dim3(WW/64, HH/8, BB), 256>>>(sa_w, sa_b);
    finalize_kernel   <<<(BB*CC*HWX/4 + 255)/256, 256>>>(out);
}

// round 4
// speedup vs baseline: 1.5414x; 1.0695x over previous
#include <cuda_runtime.h>
#include <math.h>

#define BB   4
#define CC   64
#define HH   192
#define WW   192
#define HWX  (HH*WW)
#define OFFC 18
#define HID  4

// scratch (device globals; allocations are forbidden)
__device__ float g_off[BB*OFFC*HH*WW];        // 10.6 MB
__device__ float g_h  [BB*CC*HH*WW];          // 37.7 MB
__device__ float g_pool[BB*CC];               // post-BN channel sums
__device__ float g_cw  [BB*CC];
__device__ float g_dwT  [9*CC*CC];            // [kk][o][c]
__device__ float g_offwT[CC*9*OFFC];          // [(c*9+t)*18 + o]

// dynamic smem layout for deform kernel (in floats)
#define DW_S_OFF    0                          // 4096 floats
#define SAMP_S_OFF  (DW_S_OFF + CC*CC)         // 8448 floats (64*132)
#define MWY_OFF     (SAMP_S_OFF + CC*132)      // 1152
#define MWX_OFF     (MWY_OFF + 9*128)          // 1152
#define MY0_OFF     (MWX_OFF + 9*128)          // 1152 (as int)
#define MX0_OFF     (MY0_OFF + 9*128)          // 1152 (as int)
#define DEFORM_SMEM_FLOATS (MX0_OFF + 9*128)
#define DEFORM_SMEM_BYTES  (DEFORM_SMEM_FLOATS * 4)   // 68608

// ---------------------------------------------------------------------------
// K0: weight transposes + zero pool accumulators (once per launch; tiny)
// ---------------------------------------------------------------------------
__global__ __launch_bounds__(256) void transpose_w_kernel(
        const float* __restrict__ dw, const float* __restrict__ off_w) {
    int d = blockIdx.x*256 + threadIdx.x;
    if (blockIdx.x == 0) g_pool[threadIdx.x] = 0.f;
    if (d < 9*CC*CC) {
        int kk = d >> 12;
        int o  = (d >> 6) & 63;
        int c  = d & 63;
        g_dwT[d] = dw[(o*CC + c)*9 + kk];
    } else {
        int e = d - 9*CC*CC;
        if (e < CC*9*OFFC) {
            int k = e / OFFC;      // c*9+t
            int o = e % OFFC;
            int c = k / 9, t = k % 9;
            g_offwT[e] = off_w[(o*CC + c)*9 + t];
        }
    }
}

// ---------------------------------------------------------------------------
// K1: 3x3 conv 64 -> 18 (offset prediction), pad 1
// tile 64x8, 256 threads, 2 pixels/thread (x and x+32); grid (3, 24, 4)
// ---------------------------------------------------------------------------
__global__ __launch_bounds__(256) void offset_conv_kernel(
        const float* __restrict__ x,
        const float* __restrict__ off_b) {
    __shared__ float wsm[CC*9*OFFC];   // [(c*9+t)*18+o]  41.5 KB
    __shared__ float xs[10*66];

    const int tid = threadIdx.x;
    const int bx = blockIdx.x, by = blockIdx.y, b = blockIdx.z;
    const int lx = tid & 31, ly = tid >> 5;
    const int xg0 = bx*64 + lx;
    const int yg = by*8 + ly;

    for (int t = tid; t < CC*9*OFFC/4; t += 256)
        ((float4*)wsm)[t] = ((const float4*)g_offwT)[t];

    float acc[OFFC][2];
    #pragma unroll
    for (int o = 0; o < OFFC; ++o) { float bv = off_b[o]; acc[o][0] = bv; acc[o][1] = bv; }

    const float* xb = x + (size_t)b*CC*HWX;

    #pragma unroll 1
    for (int c = 0; c < CC; ++c) {
        __syncthreads();
        for (int t = tid; t < 660; t += 256) {
            int r = t / 66, q = t % 66;
            int gy = by*8 + r - 1, gx = bx*64 + q - 1;
            float v = 0.f;
            if (gy >= 0 && gy < HH && gx >= 0 && gx < WW)
                v = xb[c*HWX + gy*WW + gx];
            xs[t] = v;
        }
        __syncthreads();
        const float* wc = wsm + c*9*OFFC;
        #pragma unroll
        for (int t = 0; t < 9; ++t) {
            int i = t/3, j = t%3;
            float xa  = xs[(ly+i)*66 + lx + j];
            float xc2 = xs[(ly+i)*66 + lx + 32 + j];
            const float2* w2 = (const float2*)(wc + t*OFFC);
            #pragma unroll
            for (int o2 = 0; o2 < 9; ++o2) {
                float2 w = w2[o2];
                acc[2*o2  ][0] += w.x*xa; acc[2*o2  ][1] += w.x*xc2;
                acc[2*o2+1][0] += w.y*xa; acc[2*o2+1][1] += w.y*xc2;
            }
        }
    }
    #pragma unroll
    for (int o = 0; o < OFFC; ++o) {
        g_off[((b*OFFC + o)*HH + yg)*WW + xg0     ] = acc[o][0];
        g_off[((b*OFFC + o)*HH + yg)*WW + xg0 + 32] = acc[o][1];
    }
}

// ---------------------------------------------------------------------------
// K2: deformable 3x3 conv 64->64 + BatchNorm + fused global-pool partial sums
// block = 2 rows x 64 px = 128 pixels, all 64 out channels; 256 threads,
// 4 adjacent pixels x 8 outputs per thread; grid (3, 96, 4); dynamic smem
// ---------------------------------------------------------------------------
__global__ __launch_bounds__(256) void deform_bn_kernel(
        const float* __restrict__ x,
        const float* __restrict__ db,
        const float* __restrict__ gma,
        const float* __restrict__ bta,
        const float* __restrict__ mean,
        const float* __restrict__ var) {
    extern __shared__ __align__(16) float smem[];
    float* dw_s   = smem + DW_S_OFF;     // one tap [o][c]: 16 KB
    float* samp_s = smem + SAMP_S_OFF;   // [c][pixel 0..127], pad to 132
    float* m_wy   = smem + MWY_OFF;
    float* m_wx   = smem + MWX_OFF;
    int*   m_y0   = (int*)(smem + MY0_OFF);
    int*   m_x0   = (int*)(smem + MX0_OFF);

    const int tid = threadIdx.x;
    const int b   = blockIdx.z;
    const int y0  = blockIdx.y * 2;
    const int x0b = blockIdx.x * 64;
    const int pq  = tid & 31;        // pixel-quad index: pixels 4pq..4pq+3
    const int og  = tid >> 5;        // output-channel group 0..7
    const int ppg = tid & 127;       // gather pixel 0..127
    const int cg  = tid >> 7;        // gather channel parity 0..1

    const float* xb   = x     + (size_t)b*CC*HWX;
    const float* offb = g_off + (size_t)b*OFFC*HWX;

    // bilinear metadata for all 9 taps x 128 pixels
    for (int t = tid; t < 9*128; t += 256) {
        int kk = t >> 7, p = t & 127;
        int row = p >> 6, col = p & 63;
        int yy = y0 + row, xx = x0b + col;
        int i = kk/3, j = kk%3;
        float oy = offb[(2*kk  )*HWX + yy*WW + xx];
        float ox = offb[(2*kk+1)*HWX + yy*WW + xx];
        float py = (float)(yy + i - 1) + oy;
        float px = (float)(xx + j - 1) + ox;
        float fy = floorf(py), fx = floorf(px);
        m_y0[t] = (int)fy;  m_x0[t] = (int)fx;
        m_wy[t] = py - fy;  m_wx[t] = px - fx;
    }

    float acc[8][4];
    #pragma unroll
    for (int r = 0; r < 8; ++r) {
        float bv = db[og*8 + r];
        acc[r][0] = bv; acc[r][1] = bv; acc[r][2] = bv; acc[r][3] = bv;
    }

    __syncthreads();

    #pragma unroll 1
    for (int kk = 0; kk < 9; ++kk) {
        // ---- gather 64x128 samples (32 per thread, fixed pixel) ----
        {
            int mi = kk*128 + ppg;
            int yq = m_y0[mi], xq = m_x0[mi];
            float wy = m_wy[mi], wx = m_wx[mi];
            float vy0 = ((unsigned)yq     < (unsigned)HH) ? 1.f : 0.f;
            float vy1 = ((unsigned)(yq+1) < (unsigned)HH) ? 1.f : 0.f;
            float vx0 = ((unsigned)xq     < (unsigned)WW) ? 1.f : 0.f;
            float vx1 = ((unsigned)(xq+1) < (unsigned)WW) ? 1.f : 0.f;
            float w00 = (1.f-wy)*(1.f-wx)*vy0*vx0;
            float w01 = (1.f-wy)*wx      *vy0*vx1;
            float w10 = wy*(1.f-wx)      *vy1*vx0;
            float w11 = wy*wx            *vy1*vx1;
            int yc0 = min(max(yq,   0), HH-1);
            int yc1 = min(max(yq+1, 0), HH-1);
            int xc0 = min(max(xq,   0), WW-1);
            int xc1 = min(max(xq+1, 0), WW-1);
            int o00 = yc0*WW + xc0, o01 = yc0*WW + xc1;
            int o10 = yc1*WW + xc0, o11 = yc1*WW + xc1;
            const float* xc = xb + cg*HWX;
            #pragma unroll
            for (int r = 0; r < 32; ++r) {
                float v = w00*xc[o00] + w01*xc[o01] + w10*xc[o10] + w11*xc[o11];
                samp_s[(2*r + cg)*132 + ppg] = v;
                xc += 2*HWX;
            }
        }
        // ---- stage this tap's weights (coalesced, pre-transposed) ----
        for (int t = tid; t < 1024; t += 256)
            ((float4*)dw_s)[t] = ((const float4*)g_dwT)[kk*1024 + t];
        __syncthreads();

        // ---- register-tiled GEMM: acc[o][p] += dw[o][c] * samp[c][p] ----
        const float4* dw4 = (const float4*)dw_s;
        #pragma unroll 4
        for (int c4 = 0; c4 < 16; ++c4) {
            float4 s0 = *(const float4*)&samp_s[(4*c4+0)*132 + 4*pq];
            float4 s1 = *(const float4*)&samp_s[(4*c4+1)*132 + 4*pq];
            float4 s2 = *(const float4*)&samp_s[(4*c4+2)*132 + 4*pq];
            float4 s3 = *(const float4*)&samp_s[(4*c4+3)*132 + 4*pq];
            #pragma unroll
            for (int r = 0; r < 8; ++r) {
                float4 w = dw4[(og*8 + r)*16 + c4];
                acc[r][0] += w.x*s0.x + w.y*s1.x + w.z*s2.x + w.w*s3.x;
                acc[r][1] += w.x*s0.y + w.y*s1.y + w.z*s2.y + w.w*s3.y;
                acc[r][2] += w.x*s0.z + w.y*s1.z + w.z*s2.z + w.w*s3.z;
                acc[r][3] += w.x*s0.w + w.y*s1.w + w.z*s2.w + w.w*s3.w;
            }
        }
        __syncthreads();
    }

    // epilogue: BN, store, fused pool partial sums
    const int p0 = 4*pq;
    const int row = p0 >> 6, col = p0 & 63;
    #pragma unroll
    for (int r = 0; r < 8; ++r) {
        int o = og*8 + r;
        float inv = rsqrtf(var[o] + 1e-5f);
        float sc = gma[o]*inv, mu = mean[o], bt = bta[o];
        float4 v;
        v.x = (acc[r][0] - mu)*sc + bt;
        v.y = (acc[r][1] - mu)*sc + bt;
        v.z = (acc[r][2] - mu)*sc + bt;
        v.w = (acc[r][3] - mu)*sc + bt;
        *(float4*)&g_h[((b*CC + o)*HH + y0 + row)*WW + x0b + col] = v;
        float s = (v.x + v.y) + (v.z + v.w);
        #pragma unroll
        for (int off = 16; off > 0; off >>= 1)
            s += __shfl_xor_sync(0xffffffffu, s, off);
        if (pq == 0) atomicAdd(&g_pool[b*CC + o], s);
    }
}

// ---------------------------------------------------------------------------
// K3: SE MLP (hid=4): one block (scales pooled sums by 1/HW)
// ---------------------------------------------------------------------------
__global__ __launch_bounds__(256) void ca_kernel(
        const float* __restrict__ w1, const float* __restrict__ b1,
        const float* __restrict__ w2, const float* __restrict__ b2) {
    __shared__ float t[BB*HID];
    const int tid = threadIdx.x;
    const int b = tid >> 6, c = tid & 63;
    if (c < HID) {
        float s = b1[c];
        for (int cc = 0; cc < CC; ++cc)
            s += w1[c*CC + cc] * (g_pool[b*CC + cc] * (1.f/(float)HWX));
        t[b*HID + c] = fmaxf(s, 0.f);
    }
    __syncthreads();
    float s = b2[c];
    #pragma unroll
    for (int h = 0; h < HID; ++h) s += w2[c*HID + h] * t[b*HID + h];
    g_cw[tid] = 1.f / (1.f + expf(-s));
}

// ---------------------------------------------------------------------------
// K4: spatial attention 7x7 conv -> sigmoid -> fused final output
// tile 64x8, 256 threads, 2 pixels/thread (x and x+32); grid (3, 24, 4)
// ---------------------------------------------------------------------------
__global__ __launch_bounds__(256) void sa_final_kernel(
        const float* __restrict__ sa_w, const float* __restrict__ sa_b,
        float* __restrict__ out) {
    __shared__ float ws[CC*49];
    __shared__ float xs[14*70];
    __shared__ float cws[CC];
    const int tid = threadIdx.x;
    const int bx = blockIdx.x, by = blockIdx.y, b = blockIdx.z;
    const int lx = tid & 31, ly = tid >> 5;
    const int xg0 = bx*64 + lx, yg = by*8 + ly;

    for (int t = tid; t < CC*49; t += 256) ws[t] = sa_w[t];
    if (tid < CC) cws[tid] = g_cw[b*CC + tid];

    float acc0 = sa_b[0], acc1 = sa_b[0];
    const float* hb = g_h + (size_t)b*CC*HWX;

    #pragma unroll 1
    for (int c = 0; c < CC; ++c) {
        __syncthreads();
        for (int t = tid; t < 14*70; t += 256) {
            int r = t / 70, q = t % 70;
            int gy = by*8 + r - 3, gx = bx*64 + q - 3;
            float v = 0.f;
            if (gy >= 0 && gy < HH && gx >= 0 && gx < WW)
                v = hb[c*HWX + gy*WW + gx];
            xs[t] = v;
        }
        __syncthreads();
        float s0 = 0.f, s1 = 0.f;
        #pragma unroll
        for (int dy = 0; dy < 7; ++dy) {
            #pragma unroll
            for (int dx = 0; dx < 7; ++dx) {
                float w = ws[c*49 + dy*7 + dx];
                s0 += xs[(ly+dy)*70 + lx + dx     ] * w;
                s1 += xs[(ly+dy)*70 + lx + 32 + dx] * w;
            }
        }
        acc0 += s0 * cws[c];
        acc1 += s1 * cws[c];
    }
    float sw0 = 1.f / (1.f + expf(-acc0));
    float sw1 = 1.f / (1.f + expf(-acc1));

    // fused finalize: out = h * cw * sw for all 64 channels of this tile
    const int base = yg*WW + xg0;
    #pragma unroll 4
    for (int c = 0; c < CC; ++c) {
        float cw = cws[c];
        float h0 = hb[c*HWX + base];
        float h1 = hb[c*HWX + base + 32];
        out[((size_t)(b*CC + c))*HWX + base     ] = h0*cw*sw0;
        out[((size_t)(b*CC + c))*HWX + base + 32] = h1*cw*sw1;
    }
}

// ---------------------------------------------------------------------------
extern "C" void kernel_launch(void* const* d_in, const int* in_sizes, int n_in,
                              void* d_out, int out_size) {
    const float* x      = (const float*)d_in[0];
    const float* off_w  = (const float*)d_in[1];
    const float* off_b  = (const float*)d_in[2];
    const float* dw     = (const float*)d_in[3];
    const float* db     = (const float*)d_in[4];
    const float* bn_g   = (const float*)d_in[5];
    const float* bn_b   = (const float*)d_in[6];
    const float* bn_m   = (const float*)d_in[7];
    const float* bn_v   = (const float*)d_in[8];
    const float* ca_w1  = (const float*)d_in[9];
    const float* ca_b1  = (const float*)d_in[10];
    const float* ca_w2  = (const float*)d_in[11];
    const float* ca_b2  = (const float*)d_in[12];
    const float* sa_w   = (const float*)d_in[13];
    const float* sa_b   = (const float*)d_in[14];
    float* out = (float*)d_out;

    cudaFuncSetAttribute(deform_bn_kernel,
                         cudaFuncAttributeMaxDynamicSharedMemorySize,
                         DEFORM_SMEM_BYTES);

    transpose_w_kernel<<<(9*CC*CC + CC*9*OFFC + 255)/256, 256>>>(dw, off_w);
    offset_conv_kernel<<<dim3(WW/64, HH/8, BB), 256>>>(x, off_b);
    deform_bn_kernel  <<<dim3(WW/64, HH/2, BB), 256, DEFORM_SMEM_BYTES>>>(
                          x, db, bn_g, bn_b, bn_m, bn_v);
    ca_kernel         <<<1, 256>>>(ca_w1, ca_b1, ca_w2, ca_b2);
    sa_final_kernel   <<<dim3(WW/64, HH/8, BB), 256>>>(sa_w, sa_b, out);
}